// round 8
// baseline (speedup 1.0000x reference)
#include <cuda_runtime.h>
#include <cstdint>

#define BN 32
#define AN 8400
#define CN 80
#define MN 64
#define TK 13
#define EPSF 1e-9f

// ---------------- scratch (device globals; no allocation) ----------------
__device__ int   d_claim[BN*AN];     // (cnt<<16) | sum_of_m
__device__ float d_maxmet[BN*MN];
__device__ float d_maxiou[BN*MN];
__device__ int   d_ma[BN*AN];
__device__ float d_alignv[BN*AN];

// ---------------- init ----------------
__global__ void k_init() {
    int idx = blockIdx.x*blockDim.x + threadIdx.x;
    if (idx < BN*AN) d_claim[idx] = 0;
    if (idx < BN*MN) { d_maxmet[idx] = 0.f; d_maxiou[idx] = 0.f; }
}

// ---------------- fused top-13: warp per (b, gt) ----------------
__global__ void __launch_bounds__(256)
k_topk(const float* __restrict__ ps, const float* __restrict__ pb,
       const float* __restrict__ ap, const int* __restrict__ gl,
       const float* __restrict__ gb, const float* __restrict__ pad)
{
    const int w    = (blockIdx.x * blockDim.x + threadIdx.x) >> 5;
    const int lane = threadIdx.x & 31;
    if (w >= BN*MN) return;
    const int b = w >> 6;
    const int m = w & 63;
    if (pad[b*MN + m] < 0.5f) return;            // padded gt: whole warp exits

    const float4 g = reinterpret_cast<const float4*>(gb)[b*MN + m];
    const float gar = fmaxf(g.z - g.x, 0.f) * fmaxf(g.w - g.y, 0.f);
    const int lab = gl[b*MN + m];

    const float4* pb4 = reinterpret_cast<const float4*>(pb) + (size_t)b*AN;
    const float2* ap2 = reinterpret_cast<const float2*>(ap);
    const float*  psb = ps + (size_t)b*AN*CN + lab;

    float tv[TK]; int ti[TK];
    #pragma unroll
    for (int k = 0; k < TK; k++) { tv[k] = 0.f; ti[k] = -1; }

    for (int a0 = 0; a0 < AN; a0 += 32) {
        const int a = a0 + lane;
        bool inside = false;
        if (a < AN) {
            float2 pt = ap2[a];
            float dmin = fminf(fminf(pt.x - g.x, pt.y - g.y),
                               fminf(g.z - pt.x, g.w - pt.y));
            inside = dmin > EPSF;
        }
        if (__ballot_sync(0xffffffffu, inside)) {  // slow path only when needed
            float metr = 0.f;
            if (inside) {
                float4 p = pb4[a];
                float parea = fmaxf(p.z - p.x, 0.f) * fmaxf(p.w - p.y, 0.f);
                float ox = fminf(g.z, p.z) - fmaxf(g.x, p.x);
                float oy = fminf(g.w, p.w) - fmaxf(g.y, p.y);
                float ov = fmaxf(ox, 0.f) * fmaxf(oy, 0.f);
                float iou = __fdividef(ov, gar + parea - ov + EPSF);
                float s = __ldg(psb + (size_t)a*CN);
                float i2 = iou * iou;
                metr = s * (i2 * i2 * i2);         // score^1 * iou^6
            }
            if (metr > tv[TK-1]) {                 // stable: ties keep earlier index
                tv[TK-1] = metr; ti[TK-1] = a;
                #pragma unroll
                for (int k = TK-1; k > 0; --k) {
                    if (tv[k] > tv[k-1]) {
                        float x = tv[k]; tv[k] = tv[k-1]; tv[k-1] = x;
                        int   y = ti[k]; ti[k] = ti[k-1]; ti[k-1] = y;
                    }
                }
            }
        }
    }

    // warp merge: extract global top-13 (value desc, tie -> lower anchor index)
    #pragma unroll
    for (int r = 0; r < TK; r++) {
        float v = tv[0]; int idx = ti[0];
        #pragma unroll
        for (int o = 16; o; o >>= 1) {
            float ov = __shfl_xor_sync(0xffffffffu, v, o);
            int   oi = __shfl_xor_sync(0xffffffffu, idx, o);
            if (ov > v || (ov == v && (unsigned)oi < (unsigned)idx)) { v = ov; idx = oi; }
        }
        if (v <= 0.f) break;                      // uniform across warp
        if (idx == ti[0]) {                       // winner lane (anchor ids unique per lane)
            atomicAdd(&d_claim[b*AN + idx], (1 << 16) + m);
            #pragma unroll
            for (int j = 0; j < TK-1; j++) { tv[j] = tv[j+1]; ti[j] = ti[j+1]; }
            tv[TK-1] = 0.f; ti[TK-1] = -1;
        }
    }
}

// ---------------- per-anchor assignment ----------------
__global__ void k_assign(const float* __restrict__ ps, const float* __restrict__ pb,
                         const int* __restrict__ gl, const float* __restrict__ gb,
                         const int* __restrict__ bgp,
                         float* __restrict__ outL, float* __restrict__ outB)
{
    __shared__ float4 s_gbox[MN];
    __shared__ float  s_gar[MN];
    __shared__ int    s_lab[MN];
    int b = blockIdx.y;
    int tid = threadIdx.x;
    if (tid < MN) {
        float4 g = reinterpret_cast<const float4*>(gb)[b*MN + tid];
        s_gbox[tid] = g;
        s_gar[tid] = fmaxf(g.z - g.x, 0.f) * fmaxf(g.w - g.y, 0.f);
        s_lab[tid] = gl[b*MN + tid];
    }
    __syncthreads();
    int a = blockIdx.x*blockDim.x + tid;
    if (a >= AN) return;
    int idx = b*AN + a;
    int claim = d_claim[idx];
    int c = claim >> 16;
    float4 p = reinterpret_cast<const float4*>(pb)[idx];
    float parea = fmaxf(p.z - p.x, 0.f) * fmaxf(p.w - p.y, 0.f);

    int m_a;
    if (c == 0) m_a = -1;
    else if (c == 1) m_a = claim & 0xffff;
    else {                                      // multi: argmax IoU over ALL gts (incl. padded)
        float best = -1.f; int bi2 = 0;
        for (int m = 0; m < MN; m++) {
            float4 g = s_gbox[m];
            float ox = fminf(g.z, p.z) - fmaxf(g.x, p.x);
            float oy = fminf(g.w, p.w) - fmaxf(g.y, p.y);
            float ov = fmaxf(ox, 0.f) * fmaxf(oy, 0.f);
            float iou = __fdividef(ov, s_gar[m] + parea - ov + EPSF);
            if (iou > best) { best = iou; bi2 = m; }
        }
        m_a = bi2;
    }

    float alignv = 0.f;
    if (m_a >= 0) {
        float4 g = s_gbox[m_a];
        float ox = fminf(g.z, p.z) - fmaxf(g.x, p.x);
        float oy = fminf(g.w, p.w) - fmaxf(g.y, p.y);
        float ov = fmaxf(ox, 0.f) * fmaxf(oy, 0.f);
        float iou = __fdividef(ov, s_gar[m_a] + parea - ov + EPSF);
        float s = __ldg(ps + (size_t)idx*CN + s_lab[m_a]);
        float i2 = iou * iou;
        alignv = s * (i2 * i2 * i2);
        atomicMax((int*)&d_maxmet[b*MN + m_a], __float_as_int(alignv)); // values >= 0
        atomicMax((int*)&d_maxiou[b*MN + m_a], __float_as_int(iou));
    }
    d_ma[idx] = m_a;
    d_alignv[idx] = alignv;

    int mm = (m_a >= 0) ? m_a : 0;              // bg anchors take gt 0 box (argmax of zeros)
    int bgv = bgp ? *bgp : 80;
    outL[idx] = (m_a >= 0) ? (float)s_lab[m_a] : (float)bgv;
    float4 g = s_gbox[mm];
    reinterpret_cast<float4*>(outB)[idx] = g;
}

// ---------------- fused scale + vectorized score write ----------------
__global__ void k_scores(const int* __restrict__ gl, float* __restrict__ outS) {
    int idx = blockIdx.x*blockDim.x + threadIdx.x;   // over B*A*C/4 float4s
    if (idx >= BN*AN*CN/4) return;
    int a  = idx / (CN/4);
    int c0 = (idx - a*(CN/4))*4;
    int m_a = d_ma[a];
    float s = 0.f; int col = -1;
    if (m_a >= 0) {
        int b = a / AN;
        int bm = b*MN + m_a;
        s = __fdividef(d_alignv[a], d_maxmet[bm] + EPSF) * d_maxiou[bm];
        col = gl[bm];
    }
    float4 v;
    v.x = (c0   == col) ? s : 0.f;
    v.y = (c0+1 == col) ? s : 0.f;
    v.z = (c0+2 == col) ? s : 0.f;
    v.w = (c0+3 == col) ? s : 0.f;
    reinterpret_cast<float4*>(outS)[idx] = v;
}

// ---------------- launch ----------------
extern "C" void kernel_launch(void* const* d_in, const int* in_sizes, int n_in,
                              void* d_out, int out_size)
{
    const float* ps  = (const float*)d_in[0];   // pred_scores  (B,A,C)
    const float* pb  = (const float*)d_in[1];   // pred_bboxes  (B,A,4)
    const float* ap  = (const float*)d_in[2];   // anchor_points(A,2)
    const int*   gl  = (const int*)d_in[3];     // gt_labels    (B,M,1)
    const float* gb  = (const float*)d_in[4];   // gt_bboxes    (B,M,4)
    const float* pad = (const float*)d_in[5];   // pad_gt_mask  (B,M,1)
    const int*   bg  = (n_in >= 7) ? (const int*)d_in[6] : nullptr;

    float* outL = (float*)d_out;                       // labels  (B*A)
    float* outB = outL + (size_t)BN*AN;                // bboxes  (B*A*4)
    float* outS = outL + (size_t)BN*AN*5;              // scores  (B*A*C)

    k_init   <<<(BN*AN + 255)/256, 256>>>();
    k_topk   <<<(BN*MN*32 + 255)/256, 256>>>(ps, pb, ap, gl, gb, pad);
    k_assign <<<dim3((AN + 255)/256, BN), 256>>>(ps, pb, gl, gb, bg, outL, outB);
    k_scores <<<(BN*AN*CN/4 + 255)/256, 256>>>(gl, outS);
}

// round 10
// speedup vs baseline: 2.4181x; 2.4181x over previous
#include <cuda_runtime.h>
#include <cstdint>

#define BN 32
#define AN 8400
#define CN 80
#define MN 64
#define TK 13
#define EPSF 1e-9f
#define NB 32                 // bins per dim
#define BINV 0.05f            // 1 / 20px
#define NBINS (NB*NB)

// ---------------- scratch (device globals; no allocation) ----------------
__device__ int    d_claim[BN*AN];     // (cnt<<16) | sum_of_m
__device__ float  d_maxmet[BN*MN];
__device__ float  d_maxiou[BN*MN];
__device__ int    d_ma[BN*AN];
__device__ float  d_alignv[BN*AN];
__device__ float2 d_scol[BN*AN];      // {scale, (float)col}
__device__ int    d_binstart[NBINS+1];
__device__ float2 d_bin_pt[AN];
__device__ int    d_bin_aid[AN];

// ---------------- init ----------------
__global__ void k_init() {
    int idx = blockIdx.x*blockDim.x + threadIdx.x;
    if (idx < BN*AN) d_claim[idx] = 0;
    if (idx < BN*MN) { d_maxmet[idx] = 0.f; d_maxiou[idx] = 0.f; }
}

// ---------------- bin anchors (single block, smem count/scan/scatter) ------
__global__ void __launch_bounds__(1024)
k_bin(const float* __restrict__ ap)
{
    __shared__ int s_cnt[NBINS];
    __shared__ int s_cur[NBINS];
    __shared__ int s_wsum[32];
    const int tid = threadIdx.x;
    const int lane = tid & 31, wid = tid >> 5;
    const float2* ap2 = reinterpret_cast<const float2*>(ap);

    s_cnt[tid] = 0;
    __syncthreads();
    for (int i = tid; i < AN; i += 1024) {
        float2 pt = ap2[i];
        int bx = min(NB-1, max(0, (int)(pt.x * BINV)));
        int by = min(NB-1, max(0, (int)(pt.y * BINV)));
        atomicAdd(&s_cnt[by*NB + bx], 1);
    }
    __syncthreads();
    // exclusive scan of 1024 counts
    int v = s_cnt[tid];
    int x = v;
    #pragma unroll
    for (int o = 1; o < 32; o <<= 1) {
        int y = __shfl_up_sync(0xffffffffu, x, o);
        if (lane >= o) x += y;
    }
    if (lane == 31) s_wsum[wid] = x;
    __syncthreads();
    if (wid == 0) {
        int s = s_wsum[lane];
        #pragma unroll
        for (int o = 1; o < 32; o <<= 1) {
            int y = __shfl_up_sync(0xffffffffu, s, o);
            if (lane >= o) s += y;
        }
        s_wsum[lane] = s;
    }
    __syncthreads();
    int incl = x + (wid > 0 ? s_wsum[wid-1] : 0);
    int excl = incl - v;
    d_binstart[tid] = excl;
    if (tid == 1023) d_binstart[NBINS] = incl;   // == AN
    s_cur[tid] = excl;
    __syncthreads();
    for (int i = tid; i < AN; i += 1024) {
        float2 pt = ap2[i];
        int bx = min(NB-1, max(0, (int)(pt.x * BINV)));
        int by = min(NB-1, max(0, (int)(pt.y * BINV)));
        int pos = atomicAdd(&s_cur[by*NB + bx], 1);
        d_bin_pt[pos] = pt;
        d_bin_aid[pos] = i;
    }
}

// ---------------- top-13: warp per (b, gt), bin-pruned candidates ----------
__global__ void __launch_bounds__(256)
k_topk(const float* __restrict__ ps, const float* __restrict__ pb,
       const int* __restrict__ gl, const float* __restrict__ gb,
       const float* __restrict__ pad)
{
    const int w    = (blockIdx.x * blockDim.x + threadIdx.x) >> 5;
    const int lane = threadIdx.x & 31;
    if (w >= BN*MN) return;
    const int b = w >> 6;
    const int m = w & 63;
    if (pad[b*MN + m] < 0.5f) return;            // padded gt: whole warp exits

    const float4 g = reinterpret_cast<const float4*>(gb)[b*MN + m];
    const float gar = fmaxf(g.z - g.x, 0.f) * fmaxf(g.w - g.y, 0.f);
    const int lab = gl[b*MN + m];

    const float4* pb4 = reinterpret_cast<const float4*>(pb) + (size_t)b*AN;
    const float*  psb = ps + (size_t)b*AN*CN + lab;

    const int c0 = min(NB-1, max(0, (int)(g.x * BINV)));
    const int c1 = min(NB-1, max(0, (int)(g.z * BINV)));
    const int r0 = min(NB-1, max(0, (int)(g.y * BINV)));
    const int r1 = min(NB-1, max(0, (int)(g.w * BINV)));

    float tv[TK]; int ti[TK];
    #pragma unroll
    for (int k = 0; k < TK; k++) { tv[k] = 0.f; ti[k] = -1; }

    for (int r = r0; r <= r1; r++) {
        const int s = d_binstart[r*NB + c0];
        const int e = d_binstart[r*NB + c1 + 1];   // contiguous span across bin cols
        for (int i0 = s; i0 < e; i0 += 32) {
            const int i = i0 + lane;
            bool inside = false;
            if (i < e) {
                float2 pt = d_bin_pt[i];
                float dmin = fminf(fminf(pt.x - g.x, pt.y - g.y),
                                   fminf(g.z - pt.x, g.w - pt.y));
                inside = dmin > EPSF;
            }
            if (__ballot_sync(0xffffffffu, inside)) {
                float metr = 0.f; int aid = -1;
                if (inside) {
                    aid = d_bin_aid[i];
                    float4 p = pb4[aid];
                    float parea = fmaxf(p.z - p.x, 0.f) * fmaxf(p.w - p.y, 0.f);
                    float ox = fminf(g.z, p.z) - fmaxf(g.x, p.x);
                    float oy = fminf(g.w, p.w) - fmaxf(g.y, p.y);
                    float ov = fmaxf(ox, 0.f) * fmaxf(oy, 0.f);
                    float iou = __fdividef(ov, gar + parea - ov + EPSF);
                    float sc = __ldg(psb + (size_t)aid*CN);
                    float i2 = iou * iou;
                    metr = sc * (i2 * i2 * i2);      // score^1 * iou^6
                }
                if (metr > tv[TK-1]) {
                    tv[TK-1] = metr; ti[TK-1] = aid;
                    #pragma unroll
                    for (int k = TK-1; k > 0; --k) {
                        if (tv[k] > tv[k-1]) {
                            float x = tv[k]; tv[k] = tv[k-1]; tv[k-1] = x;
                            int   y = ti[k]; ti[k] = ti[k-1]; ti[k-1] = y;
                        }
                    }
                }
            }
        }
    }

    // warp merge: global top-13 (value desc, tie -> lower anchor index)
    #pragma unroll
    for (int rr = 0; rr < TK; rr++) {
        float v = tv[0]; int idx = ti[0];
        #pragma unroll
        for (int o = 16; o; o >>= 1) {
            float ov = __shfl_xor_sync(0xffffffffu, v, o);
            int   oi = __shfl_xor_sync(0xffffffffu, idx, o);
            if (ov > v || (ov == v && (unsigned)oi < (unsigned)idx)) { v = ov; idx = oi; }
        }
        if (v <= 0.f) break;                      // uniform across warp
        if (idx == ti[0]) {                       // unique winner lane
            atomicAdd(&d_claim[b*AN + idx], (1 << 16) + m);
            #pragma unroll
            for (int j = 0; j < TK-1; j++) { tv[j] = tv[j+1]; ti[j] = ti[j+1]; }
            tv[TK-1] = 0.f; ti[TK-1] = -1;
        }
    }
}

// ---------------- per-anchor assignment ----------------
__global__ void k_assign(const float* __restrict__ ps, const float* __restrict__ pb,
                         const int* __restrict__ gl, const float* __restrict__ gb,
                         const int* __restrict__ bgp,
                         float* __restrict__ outL, float* __restrict__ outB)
{
    __shared__ float4 s_gbox[MN];
    __shared__ float  s_gar[MN];
    __shared__ int    s_lab[MN];
    int b = blockIdx.y;
    int tid = threadIdx.x;
    if (tid < MN) {
        float4 g = reinterpret_cast<const float4*>(gb)[b*MN + tid];
        s_gbox[tid] = g;
        s_gar[tid] = fmaxf(g.z - g.x, 0.f) * fmaxf(g.w - g.y, 0.f);
        s_lab[tid] = gl[b*MN + tid];
    }
    __syncthreads();
    int a = blockIdx.x*blockDim.x + tid;
    if (a >= AN) return;
    int idx = b*AN + a;
    int claim = d_claim[idx];
    int c = claim >> 16;
    float4 p = reinterpret_cast<const float4*>(pb)[idx];
    float parea = fmaxf(p.z - p.x, 0.f) * fmaxf(p.w - p.y, 0.f);

    int m_a;
    if (c == 0) m_a = -1;
    else if (c == 1) m_a = claim & 0xffff;
    else {                                      // multi: argmax IoU over ALL gts
        float best = -1.f; int bi2 = 0;
        for (int m = 0; m < MN; m++) {
            float4 g = s_gbox[m];
            float ox = fminf(g.z, p.z) - fmaxf(g.x, p.x);
            float oy = fminf(g.w, p.w) - fmaxf(g.y, p.y);
            float ov = fmaxf(ox, 0.f) * fmaxf(oy, 0.f);
            float iou = __fdividef(ov, s_gar[m] + parea - ov + EPSF);
            if (iou > best) { best = iou; bi2 = m; }
        }
        m_a = bi2;
    }

    float alignv = 0.f;
    if (m_a >= 0) {
        float4 g = s_gbox[m_a];
        float ox = fminf(g.z, p.z) - fmaxf(g.x, p.x);
        float oy = fminf(g.w, p.w) - fmaxf(g.y, p.y);
        float ov = fmaxf(ox, 0.f) * fmaxf(oy, 0.f);
        float iou = __fdividef(ov, s_gar[m_a] + parea - ov + EPSF);
        float s = __ldg(ps + (size_t)idx*CN + s_lab[m_a]);
        float i2 = iou * iou;
        alignv = s * (i2 * i2 * i2);
        atomicMax((int*)&d_maxmet[b*MN + m_a], __float_as_int(alignv)); // values >= 0
        atomicMax((int*)&d_maxiou[b*MN + m_a], __float_as_int(iou));
    }
    d_ma[idx] = m_a;
    d_alignv[idx] = alignv;

    int mm = (m_a >= 0) ? m_a : 0;              // bg anchors take gt 0 box (argmax of zeros)
    int bgv = bgp ? *bgp : 80;
    outL[idx] = (m_a >= 0) ? (float)s_lab[m_a] : (float)bgv;
    float4 g = s_gbox[mm];
    reinterpret_cast<float4*>(outB)[idx] = g;
}

// ---------------- per-anchor scale ----------------
__global__ void k_scale(const int* __restrict__ gl) {
    int idx = blockIdx.x*blockDim.x + threadIdx.x;
    if (idx >= BN*AN) return;
    int m_a = d_ma[idx];
    float s = 0.f; float col = -1.f;
    if (m_a >= 0) {
        int b = idx / AN;
        int bm = b*MN + m_a;
        s = __fdividef(d_alignv[idx], d_maxmet[bm] + EPSF) * d_maxiou[bm];
        col = (float)gl[bm];
    }
    d_scol[idx] = make_float2(s, col);
}

// ---------------- streaming score write (86 MB) ----------------
__global__ void k_scores(float* __restrict__ outS) {
    int idx = blockIdx.x*blockDim.x + threadIdx.x;   // over B*A*C/4 float4s
    if (idx >= BN*AN*CN/4) return;
    int a  = idx / (CN/4);
    int c0 = (idx - a*(CN/4))*4;
    float2 sc = d_scol[a];
    int col = (int)sc.y;
    float s = sc.x;
    float4 v;
    v.x = (c0   == col) ? s : 0.f;
    v.y = (c0+1 == col) ? s : 0.f;
    v.z = (c0+2 == col) ? s : 0.f;
    v.w = (c0+3 == col) ? s : 0.f;
    reinterpret_cast<float4*>(outS)[idx] = v;
}

// ---------------- launch ----------------
extern "C" void kernel_launch(void* const* d_in, const int* in_sizes, int n_in,
                              void* d_out, int out_size)
{
    const float* ps  = (const float*)d_in[0];   // pred_scores  (B,A,C)
    const float* pb  = (const float*)d_in[1];   // pred_bboxes  (B,A,4)
    const float* ap  = (const float*)d_in[2];   // anchor_points(A,2)
    const int*   gl  = (const int*)d_in[3];     // gt_labels    (B,M,1)
    const float* gb  = (const float*)d_in[4];   // gt_bboxes    (B,M,4)
    const float* pad = (const float*)d_in[5];   // pad_gt_mask  (B,M,1)
    const int*   bg  = (n_in >= 7) ? (const int*)d_in[6] : nullptr;

    float* outL = (float*)d_out;                       // labels  (B*A)
    float* outB = outL + (size_t)BN*AN;                // bboxes  (B*A*4)
    float* outS = outL + (size_t)BN*AN*5;              // scores  (B*A*C)

    k_init   <<<(BN*AN + 255)/256, 256>>>();
    k_bin    <<<1, 1024>>>(ap);
    k_topk   <<<(BN*MN*32 + 255)/256, 256>>>(ps, pb, gl, gb, pad);
    k_assign <<<dim3((AN + 255)/256, BN), 256>>>(ps, pb, gl, gb, bg, outL, outB);
    k_scale  <<<(BN*AN + 255)/256, 256>>>(gl);
    k_scores <<<(BN*AN*CN/4 + 255)/256, 256>>>(outS);
}

// round 11
// speedup vs baseline: 3.2009x; 1.3237x over previous
#include <cuda_runtime.h>
#include <cstdint>

#define BN 32
#define AN 8400
#define CN 80
#define MN 64
#define TK 13
#define EPSF 1e-9f
#define NB 32                 // bins per dim
#define BINV 0.05f            // 1 / 20px
#define NBINS (NB*NB)

// ---------------- scratch (device globals; no allocation) ----------------
__device__ int    d_claim[BN*AN];     // (cnt<<16) | sum_of_m
__device__ float  d_maxmet[BN*MN];
__device__ float  d_maxiou[BN*MN];
__device__ int    d_ma[BN*AN];
__device__ float  d_alignv[BN*AN];
__device__ int    d_binstart[NBINS+1];
__device__ float2 d_bin_pt[AN];
__device__ int    d_bin_aid[AN];

// ---------------- prep: block 0 bins anchors; other blocks zero scratch ----
__global__ void __launch_bounds__(1024)
k_prep(const float* __restrict__ ap)
{
    const int tid = threadIdx.x;
    if (blockIdx.x != 0) {
        int i = (blockIdx.x - 1)*1024 + tid;
        int step = (gridDim.x - 1)*1024;
        for (; i < BN*AN; i += step) d_claim[i] = 0;
        if (blockIdx.x == 1) {
            d_maxmet[tid] = 0.f; d_maxmet[tid + 1024] = 0.f;
            d_maxiou[tid] = 0.f; d_maxiou[tid + 1024] = 0.f;
        }
        return;
    }
    __shared__ int s_cnt[NBINS];
    __shared__ int s_cur[NBINS];
    __shared__ int s_wsum[32];
    const int lane = tid & 31, wid = tid >> 5;
    const float2* ap2 = reinterpret_cast<const float2*>(ap);

    s_cnt[tid] = 0;
    __syncthreads();
    for (int i = tid; i < AN; i += 1024) {
        float2 pt = ap2[i];
        int bx = min(NB-1, max(0, (int)(pt.x * BINV)));
        int by = min(NB-1, max(0, (int)(pt.y * BINV)));
        atomicAdd(&s_cnt[by*NB + bx], 1);
    }
    __syncthreads();
    int v = s_cnt[tid];
    int x = v;
    #pragma unroll
    for (int o = 1; o < 32; o <<= 1) {
        int y = __shfl_up_sync(0xffffffffu, x, o);
        if (lane >= o) x += y;
    }
    if (lane == 31) s_wsum[wid] = x;
    __syncthreads();
    if (wid == 0) {
        int s = s_wsum[lane];
        #pragma unroll
        for (int o = 1; o < 32; o <<= 1) {
            int y = __shfl_up_sync(0xffffffffu, s, o);
            if (lane >= o) s += y;
        }
        s_wsum[lane] = s;
    }
    __syncthreads();
    int incl = x + (wid > 0 ? s_wsum[wid-1] : 0);
    int excl = incl - v;
    d_binstart[tid] = excl;
    if (tid == 1023) d_binstart[NBINS] = incl;   // == AN
    s_cur[tid] = excl;
    __syncthreads();
    for (int i = tid; i < AN; i += 1024) {
        float2 pt = ap2[i];
        int bx = min(NB-1, max(0, (int)(pt.x * BINV)));
        int by = min(NB-1, max(0, (int)(pt.y * BINV)));
        int pos = atomicAdd(&s_cur[by*NB + bx], 1);
        d_bin_pt[pos] = pt;
        d_bin_aid[pos] = i;
    }
}

// ---------------- top-13: TWO warps per (b, gt), bin-pruned ----------------
__global__ void __launch_bounds__(256)
k_topk(const float* __restrict__ ps, const float* __restrict__ pb,
       const int* __restrict__ gl, const float* __restrict__ gb,
       const float* __restrict__ pad)
{
    __shared__ float s_v[4][2][TK];
    __shared__ int   s_i[4][2][TK];
    const int wid  = threadIdx.x >> 5;
    const int lane = threadIdx.x & 31;
    const int gslot = wid >> 1;           // 4 gts per block
    const int half  = wid & 1;            // even/odd bin rows
    const int W = blockIdx.x*4 + gslot;   // global gt id, < 2048 by construction
    const int b = W >> 6;
    const int m = W & 63;
    const bool active = pad[b*MN + m] >= 0.5f;

    float4 g = make_float4(0.f,0.f,0.f,0.f);
    if (active) {
        g = reinterpret_cast<const float4*>(gb)[b*MN + m];
        const float gar = fmaxf(g.z - g.x, 0.f) * fmaxf(g.w - g.y, 0.f);
        const int lab = gl[b*MN + m];
        const float4* pb4 = reinterpret_cast<const float4*>(pb) + (size_t)b*AN;
        const float*  psb = ps + (size_t)b*AN*CN + lab;

        const int c0 = min(NB-1, max(0, (int)(g.x * BINV)));
        const int c1 = min(NB-1, max(0, (int)(g.z * BINV)));
        const int r0 = min(NB-1, max(0, (int)(g.y * BINV)));
        const int r1 = min(NB-1, max(0, (int)(g.w * BINV)));

        float tv[TK]; int ti[TK];
        #pragma unroll
        for (int k = 0; k < TK; k++) { tv[k] = 0.f; ti[k] = -1; }

        for (int r = r0 + half; r <= r1; r += 2) {
            const int s = d_binstart[r*NB + c0];
            const int e = d_binstart[r*NB + c1 + 1];   // contiguous span
            for (int i0 = s; i0 < e; i0 += 32) {
                const int i = i0 + lane;
                bool inside = false;
                if (i < e) {
                    float2 pt = d_bin_pt[i];
                    float dmin = fminf(fminf(pt.x - g.x, pt.y - g.y),
                                       fminf(g.z - pt.x, g.w - pt.y));
                    inside = dmin > EPSF;
                }
                if (__ballot_sync(0xffffffffu, inside)) {
                    float metr = 0.f; int aid = -1;
                    if (inside) {
                        aid = d_bin_aid[i];
                        float4 p = pb4[aid];
                        float parea = fmaxf(p.z - p.x, 0.f) * fmaxf(p.w - p.y, 0.f);
                        float ox = fminf(g.z, p.z) - fmaxf(g.x, p.x);
                        float oy = fminf(g.w, p.w) - fmaxf(g.y, p.y);
                        float ov = fmaxf(ox, 0.f) * fmaxf(oy, 0.f);
                        float iou = __fdividef(ov, gar + parea - ov + EPSF);
                        float sc = __ldg(psb + (size_t)aid*CN);
                        float i2 = iou * iou;
                        metr = sc * (i2 * i2 * i2);      // score^1 * iou^6
                    }
                    if (metr > tv[TK-1]) {
                        tv[TK-1] = metr; ti[TK-1] = aid;
                        #pragma unroll
                        for (int k = TK-1; k > 0; --k) {
                            if (tv[k] > tv[k-1]) {
                                float xx = tv[k]; tv[k] = tv[k-1]; tv[k-1] = xx;
                                int   yy = ti[k]; ti[k] = ti[k-1]; ti[k-1] = yy;
                            }
                        }
                    }
                }
            }
        }

        // extract this warp's top-13 into smem (value desc, tie -> lower index)
        #pragma unroll
        for (int r = 0; r < TK; r++) {
            float v = tv[0]; int idx = ti[0];
            #pragma unroll
            for (int o = 16; o; o >>= 1) {
                float ov = __shfl_xor_sync(0xffffffffu, v, o);
                int   oi = __shfl_xor_sync(0xffffffffu, idx, o);
                if (ov > v || (ov == v && (unsigned)oi < (unsigned)idx)) { v = ov; idx = oi; }
            }
            if (lane == r) { s_v[gslot][half][r] = v; s_i[gslot][half][r] = idx; }
            if (v > 0.f && idx == ti[0]) {            // unique winner lane pops
                #pragma unroll
                for (int j = 0; j < TK-1; j++) { tv[j] = tv[j+1]; ti[j] = ti[j+1]; }
                tv[TK-1] = 0.f; ti[TK-1] = -1;
            }
        }
    } else {
        if (lane < TK) { s_v[gslot][half][lane] = 0.f; s_i[gslot][half][lane] = -1; }
    }
    __syncthreads();

    // warp 0 of each pair merges the two sorted 13-lists and scatters claims
    if (half == 0 && active) {
        float v = 0.f; int idx = -1;
        if (lane < 2*TK) {
            int h = lane >= TK;
            int k = lane - h*TK;
            v = s_v[gslot][h][k];
            idx = s_i[gslot][h][k];
        }
        #pragma unroll
        for (int r = 0; r < TK; r++) {
            float rv = v; int ridx = idx;
            #pragma unroll
            for (int o = 16; o; o >>= 1) {
                float ov = __shfl_xor_sync(0xffffffffu, rv, o);
                int   oi = __shfl_xor_sync(0xffffffffu, ridx, o);
                if (ov > rv || (ov == rv && (unsigned)oi < (unsigned)ridx)) { rv = ov; ridx = oi; }
            }
            if (rv <= 0.f) break;                     // uniform
            if (v == rv && idx == ridx) {             // unique owner (anchor ids unique)
                atomicAdd(&d_claim[b*AN + idx], (1 << 16) + m);
                v = 0.f; idx = -1;
            }
        }
    }
}

// ---------------- per-anchor assignment ----------------
__global__ void k_assign(const float* __restrict__ ps, const float* __restrict__ pb,
                         const int* __restrict__ gl, const float* __restrict__ gb,
                         const int* __restrict__ bgp,
                         float* __restrict__ outL, float* __restrict__ outB)
{
    __shared__ float4 s_gbox[MN];
    __shared__ float  s_gar[MN];
    __shared__ int    s_lab[MN];
    int b = blockIdx.y;
    int tid = threadIdx.x;
    if (tid < MN) {
        float4 g = reinterpret_cast<const float4*>(gb)[b*MN + tid];
        s_gbox[tid] = g;
        s_gar[tid] = fmaxf(g.z - g.x, 0.f) * fmaxf(g.w - g.y, 0.f);
        s_lab[tid] = gl[b*MN + tid];
    }
    __syncthreads();
    int a = blockIdx.x*blockDim.x + tid;
    if (a >= AN) return;
    int idx = b*AN + a;
    int claim = d_claim[idx];
    int c = claim >> 16;
    float4 p = reinterpret_cast<const float4*>(pb)[idx];
    float parea = fmaxf(p.z - p.x, 0.f) * fmaxf(p.w - p.y, 0.f);

    int m_a;
    if (c == 0) m_a = -1;
    else if (c == 1) m_a = claim & 0xffff;
    else {                                      // multi: argmax IoU over ALL gts
        float best = -1.f; int bi2 = 0;
        for (int m = 0; m < MN; m++) {
            float4 g = s_gbox[m];
            float ox = fminf(g.z, p.z) - fmaxf(g.x, p.x);
            float oy = fminf(g.w, p.w) - fmaxf(g.y, p.y);
            float ov = fmaxf(ox, 0.f) * fmaxf(oy, 0.f);
            float iou = __fdividef(ov, s_gar[m] + parea - ov + EPSF);
            if (iou > best) { best = iou; bi2 = m; }
        }
        m_a = bi2;
    }

    float alignv = 0.f;
    if (m_a >= 0) {
        float4 g = s_gbox[m_a];
        float ox = fminf(g.z, p.z) - fmaxf(g.x, p.x);
        float oy = fminf(g.w, p.w) - fmaxf(g.y, p.y);
        float ov = fmaxf(ox, 0.f) * fmaxf(oy, 0.f);
        float iou = __fdividef(ov, s_gar[m_a] + parea - ov + EPSF);
        float s = __ldg(ps + (size_t)idx*CN + s_lab[m_a]);
        float i2 = iou * iou;
        alignv = s * (i2 * i2 * i2);
        atomicMax((int*)&d_maxmet[b*MN + m_a], __float_as_int(alignv)); // values >= 0
        atomicMax((int*)&d_maxiou[b*MN + m_a], __float_as_int(iou));
    }
    d_ma[idx] = m_a;
    d_alignv[idx] = alignv;

    int mm = (m_a >= 0) ? m_a : 0;              // bg anchors take gt 0 box (argmax of zeros)
    int bgv = bgp ? *bgp : 80;
    outL[idx] = (m_a >= 0) ? (float)s_lab[m_a] : (float)bgv;
    float4 g = s_gbox[mm];
    reinterpret_cast<float4*>(outB)[idx] = g;
}

// ---------------- fused scale + streaming score write (86 MB) --------------
__global__ void k_scores(const int* __restrict__ gl, float* __restrict__ outS) {
    int idx = blockIdx.x*blockDim.x + threadIdx.x;   // over B*A*C/4 float4s
    if (idx >= BN*AN*CN/4) return;
    int a  = idx / (CN/4);
    int c0 = (idx - a*(CN/4))*4;
    int m_a = d_ma[a];
    float s = 0.f; int col = -1;
    if (m_a >= 0) {
        int b = a / AN;
        int bm = b*MN + m_a;
        s = __fdividef(d_alignv[a], d_maxmet[bm] + EPSF) * d_maxiou[bm];
        col = gl[bm];
    }
    float4 v;
    v.x = (c0   == col) ? s : 0.f;
    v.y = (c0+1 == col) ? s : 0.f;
    v.z = (c0+2 == col) ? s : 0.f;
    v.w = (c0+3 == col) ? s : 0.f;
    reinterpret_cast<float4*>(outS)[idx] = v;
}

// ---------------- launch ----------------
extern "C" void kernel_launch(void* const* d_in, const int* in_sizes, int n_in,
                              void* d_out, int out_size)
{
    const float* ps  = (const float*)d_in[0];   // pred_scores  (B,A,C)
    const float* pb  = (const float*)d_in[1];   // pred_bboxes  (B,A,4)
    const float* ap  = (const float*)d_in[2];   // anchor_points(A,2)
    const int*   gl  = (const int*)d_in[3];     // gt_labels    (B,M,1)
    const float* gb  = (const float*)d_in[4];   // gt_bboxes    (B,M,4)
    const float* pad = (const float*)d_in[5];   // pad_gt_mask  (B,M,1)
    const int*   bg  = (n_in >= 7) ? (const int*)d_in[6] : nullptr;

    float* outL = (float*)d_out;                       // labels  (B*A)
    float* outB = outL + (size_t)BN*AN;                // bboxes  (B*A*4)
    float* outS = outL + (size_t)BN*AN*5;              // scores  (B*A*C)

    k_prep   <<<264, 1024>>>(ap);
    k_topk   <<<BN*MN*2/8, 256>>>(ps, pb, gl, gb, pad);
    k_assign <<<dim3((AN + 255)/256, BN), 256>>>(ps, pb, gl, gb, bg, outL, outB);
    k_scores <<<(BN*AN*CN/4 + 255)/256, 256>>>(gl, outS);
}

// round 12
// speedup vs baseline: 3.5161x; 1.0985x over previous
#include <cuda_runtime.h>
#include <cstdint>

#define BN 32
#define AN 8400
#define CN 80
#define MN 64
#define TK 13
#define EPSF 1e-9f
#define NB 32                 // bins per dim
#define BINV 0.05f            // 1 / 20px
#define NBINS (NB*NB)

// ---------------- scratch (device globals; no allocation) ----------------
__device__ int    d_claim[BN*AN];     // (cnt<<16) | sum_of_m
__device__ float  d_maxmet[BN*MN];
__device__ float  d_maxiou[BN*MN];
__device__ int    d_ma[BN*AN];
__device__ float  d_alignv[BN*AN];
__device__ int    d_binstart[NBINS+1];
__device__ float2 d_bin_pt[AN];
__device__ int    d_bin_aid[AN];

// ---------------- zero-fill scores: pure streaming stores ----------------
__global__ void __launch_bounds__(256)
k_zero(float4* __restrict__ outS4) {
    int base = blockIdx.x*1024 + threadIdx.x;     // grid = 5250 blocks exactly
    float4 z = make_float4(0.f,0.f,0.f,0.f);
    outS4[base      ] = z;
    outS4[base + 256] = z;
    outS4[base + 512] = z;
    outS4[base + 768] = z;
}

// ---------------- prep: block 0 bins anchors; other blocks zero scratch ----
__global__ void __launch_bounds__(1024)
k_prep(const float* __restrict__ ap)
{
    const int tid = threadIdx.x;
    if (blockIdx.x != 0) {
        int i = (blockIdx.x - 1)*1024 + tid;
        int step = (gridDim.x - 1)*1024;
        for (; i < BN*AN; i += step) d_claim[i] = 0;
        if (blockIdx.x == 1) {
            d_maxmet[tid] = 0.f; d_maxmet[tid + 1024] = 0.f;
            d_maxiou[tid] = 0.f; d_maxiou[tid + 1024] = 0.f;
        }
        return;
    }
    __shared__ int s_cnt[NBINS];
    __shared__ int s_cur[NBINS];
    __shared__ int s_wsum[32];
    const int lane = tid & 31, wid = tid >> 5;
    const float2* ap2 = reinterpret_cast<const float2*>(ap);

    s_cnt[tid] = 0;
    __syncthreads();
    for (int i = tid; i < AN; i += 1024) {
        float2 pt = ap2[i];
        int bx = min(NB-1, max(0, (int)(pt.x * BINV)));
        int by = min(NB-1, max(0, (int)(pt.y * BINV)));
        atomicAdd(&s_cnt[by*NB + bx], 1);
    }
    __syncthreads();
    int v = s_cnt[tid];
    int x = v;
    #pragma unroll
    for (int o = 1; o < 32; o <<= 1) {
        int y = __shfl_up_sync(0xffffffffu, x, o);
        if (lane >= o) x += y;
    }
    if (lane == 31) s_wsum[wid] = x;
    __syncthreads();
    if (wid == 0) {
        int s = s_wsum[lane];
        #pragma unroll
        for (int o = 1; o < 32; o <<= 1) {
            int y = __shfl_up_sync(0xffffffffu, s, o);
            if (lane >= o) s += y;
        }
        s_wsum[lane] = s;
    }
    __syncthreads();
    int incl = x + (wid > 0 ? s_wsum[wid-1] : 0);
    int excl = incl - v;
    d_binstart[tid] = excl;
    if (tid == 1023) d_binstart[NBINS] = incl;   // == AN
    s_cur[tid] = excl;
    __syncthreads();
    for (int i = tid; i < AN; i += 1024) {
        float2 pt = ap2[i];
        int bx = min(NB-1, max(0, (int)(pt.x * BINV)));
        int by = min(NB-1, max(0, (int)(pt.y * BINV)));
        int pos = atomicAdd(&s_cur[by*NB + bx], 1);
        d_bin_pt[pos] = pt;
        d_bin_aid[pos] = i;
    }
}

// ---------------- top-13: FOUR warps per (b, gt), bin-pruned ---------------
__global__ void __launch_bounds__(256)
k_topk(const float* __restrict__ ps, const float* __restrict__ pb,
       const int* __restrict__ gl, const float* __restrict__ gb,
       const float* __restrict__ pad)
{
    __shared__ float s_v[2][4][TK];
    __shared__ int   s_i[2][4][TK];
    const int wid  = threadIdx.x >> 5;
    const int lane = threadIdx.x & 31;
    const int gslot = wid >> 2;           // 2 gts per block
    const int q     = wid & 3;            // bin-row class (rows mod 4)
    const int W = blockIdx.x*2 + gslot;   // global gt id < 2048
    const int b = W >> 6;
    const int m = W & 63;
    const bool active = pad[b*MN + m] >= 0.5f;

    if (active) {
        const float4 g = reinterpret_cast<const float4*>(gb)[b*MN + m];
        const float gar = fmaxf(g.z - g.x, 0.f) * fmaxf(g.w - g.y, 0.f);
        const int lab = gl[b*MN + m];
        const float4* pb4 = reinterpret_cast<const float4*>(pb) + (size_t)b*AN;
        const float*  psb = ps + (size_t)b*AN*CN + lab;

        const int c0 = min(NB-1, max(0, (int)(g.x * BINV)));
        const int c1 = min(NB-1, max(0, (int)(g.z * BINV)));
        const int r0 = min(NB-1, max(0, (int)(g.y * BINV)));
        const int r1 = min(NB-1, max(0, (int)(g.w * BINV)));

        float tv[TK]; int ti[TK];
        #pragma unroll
        for (int k = 0; k < TK; k++) { tv[k] = 0.f; ti[k] = -1; }

        for (int r = r0 + q; r <= r1; r += 4) {
            const int s = d_binstart[r*NB + c0];
            const int e = d_binstart[r*NB + c1 + 1];   // contiguous span
            for (int i0 = s; i0 < e; i0 += 32) {
                const int i = i0 + lane;
                bool inside = false;
                if (i < e) {
                    float2 pt = d_bin_pt[i];
                    float dmin = fminf(fminf(pt.x - g.x, pt.y - g.y),
                                       fminf(g.z - pt.x, g.w - pt.y));
                    inside = dmin > EPSF;
                }
                if (__ballot_sync(0xffffffffu, inside)) {
                    float metr = 0.f; int aid = -1;
                    if (inside) {
                        aid = d_bin_aid[i];
                        float4 p = pb4[aid];
                        float parea = fmaxf(p.z - p.x, 0.f) * fmaxf(p.w - p.y, 0.f);
                        float ox = fminf(g.z, p.z) - fmaxf(g.x, p.x);
                        float oy = fminf(g.w, p.w) - fmaxf(g.y, p.y);
                        float ov = fmaxf(ox, 0.f) * fmaxf(oy, 0.f);
                        float iou = __fdividef(ov, gar + parea - ov + EPSF);
                        float sc = __ldg(psb + (size_t)aid*CN);
                        float i2 = iou * iou;
                        metr = sc * (i2 * i2 * i2);      // score^1 * iou^6
                    }
                    if (metr > tv[TK-1]) {
                        tv[TK-1] = metr; ti[TK-1] = aid;
                        #pragma unroll
                        for (int k = TK-1; k > 0; --k) {
                            if (tv[k] > tv[k-1]) {
                                float xx = tv[k]; tv[k] = tv[k-1]; tv[k-1] = xx;
                                int   yy = ti[k]; ti[k] = ti[k-1]; ti[k-1] = yy;
                            }
                        }
                    }
                }
            }
        }

        // extract this warp's sorted top-13 to smem (desc, tie -> lower index)
        #pragma unroll
        for (int r = 0; r < TK; r++) {
            float v = tv[0]; int idx = ti[0];
            #pragma unroll
            for (int o = 16; o; o >>= 1) {
                float ov = __shfl_xor_sync(0xffffffffu, v, o);
                int   oi = __shfl_xor_sync(0xffffffffu, idx, o);
                if (ov > v || (ov == v && (unsigned)oi < (unsigned)idx)) { v = ov; idx = oi; }
            }
            if (lane == r) { s_v[gslot][q][r] = v; s_i[gslot][q][r] = idx; }
            if (v > 0.f && idx == ti[0]) {            // unique winner lane pops
                #pragma unroll
                for (int j = 0; j < TK-1; j++) { tv[j] = tv[j+1]; ti[j] = ti[j+1]; }
                tv[TK-1] = 0.f; ti[TK-1] = -1;
            }
        }
    } else {
        if (lane < TK) { s_v[gslot][q][lane] = 0.f; s_i[gslot][q][lane] = -1; }
    }
    __syncthreads();

    // warp q==0 of each gt merges the 4 sorted 13-lists (52 entries, 2/lane)
    if (q == 0 && active) {
        const float* fv = &s_v[gslot][0][0];
        const int*   fi = &s_i[gslot][0][0];
        float v0 = fv[lane];        int i0 = fi[lane];           // 0..31
        float v1 = 0.f;             int i1 = -1;
        if (lane < 4*TK - 32) { v1 = fv[lane+32]; i1 = fi[lane+32]; } // 32..51
        #pragma unroll
        for (int r = 0; r < TK; r++) {
            bool p0 = (v0 > v1) || (v0 == v1 && (unsigned)i0 < (unsigned)i1);
            float lv = p0 ? v0 : v1;
            int   li = p0 ? i0 : i1;
            #pragma unroll
            for (int o = 16; o; o >>= 1) {
                float ov = __shfl_xor_sync(0xffffffffu, lv, o);
                int   oi = __shfl_xor_sync(0xffffffffu, li, o);
                if (ov > lv || (ov == lv && (unsigned)oi < (unsigned)li)) { lv = ov; li = oi; }
            }
            if (lv <= 0.f) break;                     // uniform
            if (i0 == li)      { atomicAdd(&d_claim[b*AN + li], (1 << 16) + m); v0 = 0.f; i0 = -1; }
            else if (i1 == li) { atomicAdd(&d_claim[b*AN + li], (1 << 16) + m); v1 = 0.f; i1 = -1; }
        }
    }
}

// ---------------- per-anchor assignment ----------------
__global__ void k_assign(const float* __restrict__ ps, const float* __restrict__ pb,
                         const int* __restrict__ gl, const float* __restrict__ gb,
                         const int* __restrict__ bgp,
                         float* __restrict__ outL, float* __restrict__ outB)
{
    __shared__ float4 s_gbox[MN];
    __shared__ float  s_gar[MN];
    __shared__ int    s_lab[MN];
    int b = blockIdx.y;
    int tid = threadIdx.x;
    if (tid < MN) {
        float4 g = reinterpret_cast<const float4*>(gb)[b*MN + tid];
        s_gbox[tid] = g;
        s_gar[tid] = fmaxf(g.z - g.x, 0.f) * fmaxf(g.w - g.y, 0.f);
        s_lab[tid] = gl[b*MN + tid];
    }
    __syncthreads();
    int a = blockIdx.x*blockDim.x + tid;
    if (a >= AN) return;
    int idx = b*AN + a;
    int claim = d_claim[idx];
    int c = claim >> 16;
    float4 p = reinterpret_cast<const float4*>(pb)[idx];
    float parea = fmaxf(p.z - p.x, 0.f) * fmaxf(p.w - p.y, 0.f);

    int m_a;
    if (c == 0) m_a = -1;
    else if (c == 1) m_a = claim & 0xffff;
    else {                                      // multi: argmax IoU over ALL gts
        float best = -1.f; int bi2 = 0;
        for (int m = 0; m < MN; m++) {
            float4 g = s_gbox[m];
            float ox = fminf(g.z, p.z) - fmaxf(g.x, p.x);
            float oy = fminf(g.w, p.w) - fmaxf(g.y, p.y);
            float ov = fmaxf(ox, 0.f) * fmaxf(oy, 0.f);
            float iou = __fdividef(ov, s_gar[m] + parea - ov + EPSF);
            if (iou > best) { best = iou; bi2 = m; }
        }
        m_a = bi2;
    }

    float alignv = 0.f;
    if (m_a >= 0) {
        float4 g = s_gbox[m_a];
        float ox = fminf(g.z, p.z) - fmaxf(g.x, p.x);
        float oy = fminf(g.w, p.w) - fmaxf(g.y, p.y);
        float ov = fmaxf(ox, 0.f) * fmaxf(oy, 0.f);
        float iou = __fdividef(ov, s_gar[m_a] + parea - ov + EPSF);
        float s = __ldg(ps + (size_t)idx*CN + s_lab[m_a]);
        float i2 = iou * iou;
        alignv = s * (i2 * i2 * i2);
        atomicMax((int*)&d_maxmet[b*MN + m_a], __float_as_int(alignv)); // values >= 0
        atomicMax((int*)&d_maxiou[b*MN + m_a], __float_as_int(iou));
    }
    d_ma[idx] = m_a;
    d_alignv[idx] = alignv;

    int mm = (m_a >= 0) ? m_a : 0;              // bg anchors take gt 0 box (argmax of zeros)
    int bgv = bgp ? *bgp : 80;
    outL[idx] = (m_a >= 0) ? (float)s_lab[m_a] : (float)bgv;
    float4 g = s_gbox[mm];
    reinterpret_cast<float4*>(outB)[idx] = g;
}

// ---------------- sparse score scatter (positives only) --------------------
__global__ void k_sscore(const int* __restrict__ gl, float* __restrict__ outS) {
    int idx = blockIdx.x*blockDim.x + threadIdx.x;
    if (idx >= BN*AN) return;
    int m_a = d_ma[idx];
    if (m_a < 0) return;
    int b = idx / AN;
    int bm = b*MN + m_a;
    float s = __fdividef(d_alignv[idx], d_maxmet[bm] + EPSF) * d_maxiou[bm];
    outS[(size_t)idx*CN + gl[bm]] = s;
}

// ---------------- launch ----------------
extern "C" void kernel_launch(void* const* d_in, const int* in_sizes, int n_in,
                              void* d_out, int out_size)
{
    const float* ps  = (const float*)d_in[0];   // pred_scores  (B,A,C)
    const float* pb  = (const float*)d_in[1];   // pred_bboxes  (B,A,4)
    const float* ap  = (const float*)d_in[2];   // anchor_points(A,2)
    const int*   gl  = (const int*)d_in[3];     // gt_labels    (B,M,1)
    const float* gb  = (const float*)d_in[4];   // gt_bboxes    (B,M,4)
    const float* pad = (const float*)d_in[5];   // pad_gt_mask  (B,M,1)
    const int*   bg  = (n_in >= 7) ? (const int*)d_in[6] : nullptr;

    float* outL = (float*)d_out;                       // labels  (B*A)
    float* outB = outL + (size_t)BN*AN;                // bboxes  (B*A*4)
    float* outS = outL + (size_t)BN*AN*5;              // scores  (B*A*C)

    k_zero   <<<BN*AN*CN/4/1024, 256>>>(reinterpret_cast<float4*>(outS));  // 5250 blocks
    k_prep   <<<264, 1024>>>(ap);
    k_topk   <<<BN*MN/2, 256>>>(ps, pb, gl, gb, pad);
    k_assign <<<dim3((AN + 255)/256, BN), 256>>>(ps, pb, gl, gb, bg, outL, outB);
    k_sscore <<<(BN*AN + 255)/256, 256>>>(gl, outS);
}

// round 15
// speedup vs baseline: 3.7130x; 1.0560x over previous
#include <cuda_runtime.h>
#include <cstdint>

#define BN 32
#define AN 8400
#define CN 80
#define MN 64
#define TK 13
#define EPSF 1e-9f
#define NB 32                 // bins per dim
#define BINV 0.05f            // 1 / 20px
#define NBINS (NB*NB)

// ---------------- scratch (device globals; no allocation) ----------------
__device__ int    d_claim[BN*AN];     // (cnt<<16) | sum_of_m
__device__ float  d_maxmet[BN*MN];
__device__ float  d_maxiou[BN*MN];
__device__ int    d_ma[BN*AN];
__device__ float  d_alignv[BN*AN];
__device__ int    d_binstart[NBINS+1];
__device__ float2 d_bin_pt[AN];
__device__ int    d_bin_aid[AN];

// ---------------- prep: block 0 bins anchors; other blocks zero scratch ----
__global__ void __launch_bounds__(1024)
k_prep(const float* __restrict__ ap)
{
    const int tid = threadIdx.x;
    if (blockIdx.x != 0) {
        int i = (blockIdx.x - 1)*1024 + tid;
        int step = (gridDim.x - 1)*1024;
        for (; i < BN*AN; i += step) d_claim[i] = 0;
        if (blockIdx.x == 1) {
            d_maxmet[tid] = 0.f; d_maxmet[tid + 1024] = 0.f;
            d_maxiou[tid] = 0.f; d_maxiou[tid + 1024] = 0.f;
        }
        return;
    }
    __shared__ int s_cnt[NBINS];
    __shared__ int s_cur[NBINS];
    __shared__ int s_wsum[32];
    const int lane = tid & 31, wid = tid >> 5;
    const float2* ap2 = reinterpret_cast<const float2*>(ap);

    s_cnt[tid] = 0;
    __syncthreads();
    for (int i = tid; i < AN; i += 1024) {
        float2 pt = ap2[i];
        int bx = min(NB-1, max(0, (int)(pt.x * BINV)));
        int by = min(NB-1, max(0, (int)(pt.y * BINV)));
        atomicAdd(&s_cnt[by*NB + bx], 1);
    }
    __syncthreads();
    int v = s_cnt[tid];
    int x = v;
    #pragma unroll
    for (int o = 1; o < 32; o <<= 1) {
        int y = __shfl_up_sync(0xffffffffu, x, o);
        if (lane >= o) x += y;
    }
    if (lane == 31) s_wsum[wid] = x;
    __syncthreads();
    if (wid == 0) {
        int s = s_wsum[lane];
        #pragma unroll
        for (int o = 1; o < 32; o <<= 1) {
            int y = __shfl_up_sync(0xffffffffu, s, o);
            if (lane >= o) s += y;
        }
        s_wsum[lane] = s;
    }
    __syncthreads();
    int incl = x + (wid > 0 ? s_wsum[wid-1] : 0);
    int excl = incl - v;
    d_binstart[tid] = excl;
    if (tid == 1023) d_binstart[NBINS] = incl;   // == AN
    s_cur[tid] = excl;
    __syncthreads();
    for (int i = tid; i < AN; i += 1024) {
        float2 pt = ap2[i];
        int bx = min(NB-1, max(0, (int)(pt.x * BINV)));
        int by = min(NB-1, max(0, (int)(pt.y * BINV)));
        int pos = atomicAdd(&s_cur[by*NB + bx], 1);
        d_bin_pt[pos] = pt;
        d_bin_aid[pos] = i;
    }
}

// ------- top-13 (4 warps/gt) + fused streaming zero-fill of scores ---------
__global__ void __launch_bounds__(256)
k_topk(const float* __restrict__ ps, const float* __restrict__ pb,
       const int* __restrict__ gl, const float* __restrict__ gb,
       const float* __restrict__ pad, float4* __restrict__ outS4)
{
    // striped zero of the 86 MB score tensor; stores overlap the latency-
    // bound top-k below (ordering vs k_sscore guaranteed by graph order)
    {
        const int nf4 = BN*AN*CN/4;
        const float4 z = make_float4(0.f,0.f,0.f,0.f);
        for (int i = blockIdx.x*blockDim.x + threadIdx.x; i < nf4;
             i += gridDim.x*blockDim.x)
            outS4[i] = z;
    }

    __shared__ float s_v[2][4][TK];
    __shared__ int   s_i[2][4][TK];
    const int wid  = threadIdx.x >> 5;
    const int lane = threadIdx.x & 31;
    const int gslot = wid >> 2;           // 2 gts per block
    const int q     = wid & 3;            // bin-row class (rows mod 4)
    const int W = blockIdx.x*2 + gslot;   // global gt id < 2048
    const int b = W >> 6;
    const int m = W & 63;
    const bool active = pad[b*MN + m] >= 0.5f;

    if (active) {
        const float4 g = reinterpret_cast<const float4*>(gb)[b*MN + m];
        const float gar = fmaxf(g.z - g.x, 0.f) * fmaxf(g.w - g.y, 0.f);
        const int lab = gl[b*MN + m];
        const float4* pb4 = reinterpret_cast<const float4*>(pb) + (size_t)b*AN;
        const float*  psb = ps + (size_t)b*AN*CN + lab;

        const int c0 = min(NB-1, max(0, (int)(g.x * BINV)));
        const int c1 = min(NB-1, max(0, (int)(g.z * BINV)));
        const int r0 = min(NB-1, max(0, (int)(g.y * BINV)));
        const int r1 = min(NB-1, max(0, (int)(g.w * BINV)));

        float tv[TK]; int ti[TK];
        #pragma unroll
        for (int k = 0; k < TK; k++) { tv[k] = 0.f; ti[k] = -1; }

        for (int r = r0 + q; r <= r1; r += 4) {
            const int s = d_binstart[r*NB + c0];
            const int e = d_binstart[r*NB + c1 + 1];   // contiguous span
            for (int i0 = s; i0 < e; i0 += 32) {
                const int i = i0 + lane;
                bool inside = false;
                if (i < e) {
                    float2 pt = d_bin_pt[i];
                    float dmin = fminf(fminf(pt.x - g.x, pt.y - g.y),
                                       fminf(g.z - pt.x, g.w - pt.y));
                    inside = dmin > EPSF;
                }
                if (__ballot_sync(0xffffffffu, inside)) {
                    float metr = 0.f; int aid = -1;
                    if (inside) {
                        aid = d_bin_aid[i];
                        float4 p = pb4[aid];
                        float parea = fmaxf(p.z - p.x, 0.f) * fmaxf(p.w - p.y, 0.f);
                        float ox = fminf(g.z, p.z) - fmaxf(g.x, p.x);
                        float oy = fminf(g.w, p.w) - fmaxf(g.y, p.y);
                        float ov = fmaxf(ox, 0.f) * fmaxf(oy, 0.f);
                        float iou = __fdividef(ov, gar + parea - ov + EPSF);
                        float sc = __ldg(psb + (size_t)aid*CN);
                        float i2 = iou * iou;
                        metr = sc * (i2 * i2 * i2);      // score^1 * iou^6
                    }
                    if (metr > tv[TK-1]) {
                        tv[TK-1] = metr; ti[TK-1] = aid;
                        #pragma unroll
                        for (int k = TK-1; k > 0; --k) {
                            if (tv[k] > tv[k-1]) {
                                float xx = tv[k]; tv[k] = tv[k-1]; tv[k-1] = xx;
                                int   yy = ti[k]; ti[k] = ti[k-1]; ti[k-1] = yy;
                            }
                        }
                    }
                }
            }
        }

        // extract this warp's sorted top-13 to smem (desc, tie -> lower index)
        #pragma unroll
        for (int r = 0; r < TK; r++) {
            float v = tv[0]; int idx = ti[0];
            #pragma unroll
            for (int o = 16; o; o >>= 1) {
                float ov = __shfl_xor_sync(0xffffffffu, v, o);
                int   oi = __shfl_xor_sync(0xffffffffu, idx, o);
                if (ov > v || (ov == v && (unsigned)oi < (unsigned)idx)) { v = ov; idx = oi; }
            }
            if (lane == r) { s_v[gslot][q][r] = v; s_i[gslot][q][r] = idx; }
            if (v > 0.f && idx == ti[0]) {            // unique winner lane pops
                #pragma unroll
                for (int j = 0; j < TK-1; j++) { tv[j] = tv[j+1]; ti[j] = ti[j+1]; }
                tv[TK-1] = 0.f; ti[TK-1] = -1;
            }
        }
    } else {
        if (lane < TK) { s_v[gslot][q][lane] = 0.f; s_i[gslot][q][lane] = -1; }
    }
    __syncthreads();

    // warp q==0 of each gt merges the 4 sorted 13-lists (52 entries, 2/lane)
    if (q == 0 && active) {
        const float* fv = &s_v[gslot][0][0];
        const int*   fi = &s_i[gslot][0][0];
        float v0 = fv[lane];        int i0 = fi[lane];           // 0..31
        float v1 = 0.f;             int i1 = -1;
        if (lane < 4*TK - 32) { v1 = fv[lane+32]; i1 = fi[lane+32]; } // 32..51
        #pragma unroll
        for (int r = 0; r < TK; r++) {
            bool p0 = (v0 > v1) || (v0 == v1 && (unsigned)i0 < (unsigned)i1);
            float lv = p0 ? v0 : v1;
            int   li = p0 ? i0 : i1;
            #pragma unroll
            for (int o = 16; o; o >>= 1) {
                float ov = __shfl_xor_sync(0xffffffffu, lv, o);
                int   oi = __shfl_xor_sync(0xffffffffu, li, o);
                if (ov > lv || (ov == lv && (unsigned)oi < (unsigned)li)) { lv = ov; li = oi; }
            }
            if (lv <= 0.f) break;                     // uniform
            if (i0 == li)      { atomicAdd(&d_claim[b*AN + li], (1 << 16) + m); v0 = 0.f; i0 = -1; }
            else if (i1 == li) { atomicAdd(&d_claim[b*AN + li], (1 << 16) + m); v1 = 0.f; i1 = -1; }
        }
    }
}

// ---------------- per-anchor assignment (background fast path) -------------
__global__ void k_assign(const float* __restrict__ ps, const float* __restrict__ pb,
                         const int* __restrict__ gl, const float* __restrict__ gb,
                         const int* __restrict__ bgp,
                         float* __restrict__ outL, float* __restrict__ outB)
{
    __shared__ float4 s_gbox[MN];
    __shared__ float  s_gar[MN];
    __shared__ int    s_lab[MN];
    int b = blockIdx.y;
    int tid = threadIdx.x;
    if (tid < MN) {
        float4 g = reinterpret_cast<const float4*>(gb)[b*MN + tid];
        s_gbox[tid] = g;
        s_gar[tid] = fmaxf(g.z - g.x, 0.f) * fmaxf(g.w - g.y, 0.f);
        s_lab[tid] = gl[b*MN + tid];
    }
    __syncthreads();
    int a = blockIdx.x*blockDim.x + tid;
    if (a >= AN) return;
    int idx = b*AN + a;
    int claim = d_claim[idx];
    int c = claim >> 16;

    if (c == 0) {                               // ~92%: background, no pb load
        d_ma[idx] = -1;
        outL[idx] = (float)(bgp ? *bgp : 80);
        reinterpret_cast<float4*>(outB)[idx] = s_gbox[0];  // argmax of zeros -> gt 0
        return;
    }

    float4 p = reinterpret_cast<const float4*>(pb)[idx];
    float parea = fmaxf(p.z - p.x, 0.f) * fmaxf(p.w - p.y, 0.f);

    int m_a;
    if (c == 1) m_a = claim & 0xffff;
    else {                                      // multi: argmax IoU over ALL gts
        float best = -1.f; int bi2 = 0;
        for (int m = 0; m < MN; m++) {
            float4 g = s_gbox[m];
            float ox = fminf(g.z, p.z) - fmaxf(g.x, p.x);
            float oy = fminf(g.w, p.w) - fmaxf(g.y, p.y);
            float ov = fmaxf(ox, 0.f) * fmaxf(oy, 0.f);
            float iou = __fdividef(ov, s_gar[m] + parea - ov + EPSF);
            if (iou > best) { best = iou; bi2 = m; }
        }
        m_a = bi2;
    }

    float4 g = s_gbox[m_a];
    float ox = fminf(g.z, p.z) - fmaxf(g.x, p.x);
    float oy = fminf(g.w, p.w) - fmaxf(g.y, p.y);
    float ov = fmaxf(ox, 0.f) * fmaxf(oy, 0.f);
    float iou = __fdividef(ov, s_gar[m_a] + parea - ov + EPSF);
    float s = __ldg(ps + (size_t)idx*CN + s_lab[m_a]);
    float i2 = iou * iou;
    float alignv = s * (i2 * i2 * i2);
    atomicMax((int*)&d_maxmet[b*MN + m_a], __float_as_int(alignv)); // values >= 0
    atomicMax((int*)&d_maxiou[b*MN + m_a], __float_as_int(iou));

    d_ma[idx] = m_a;
    d_alignv[idx] = alignv;
    outL[idx] = (float)s_lab[m_a];
    reinterpret_cast<float4*>(outB)[idx] = g;
}

// ---------------- sparse score scatter (positives only) --------------------
__global__ void k_sscore(const int* __restrict__ gl, float* __restrict__ outS) {
    int idx = blockIdx.x*blockDim.x + threadIdx.x;
    if (idx >= BN*AN) return;
    int m_a = d_ma[idx];
    if (m_a < 0) return;
    int b = idx / AN;
    int bm = b*MN + m_a;
    float s = __fdividef(d_alignv[idx], d_maxmet[bm] + EPSF) * d_maxiou[bm];
    outS[(size_t)idx*CN + gl[bm]] = s;
}

// ---------------- launch ----------------
extern "C" void kernel_launch(void* const* d_in, const int* in_sizes, int n_in,
                              void* d_out, int out_size)
{
    const float* ps  = (const float*)d_in[0];   // pred_scores  (B,A,C)
    const float* pb  = (const float*)d_in[1];   // pred_bboxes  (B,A,4)
    const float* ap  = (const float*)d_in[2];   // anchor_points(A,2)
    const int*   gl  = (const int*)d_in[3];     // gt_labels    (B,M,1)
    const float* gb  = (const float*)d_in[4];   // gt_bboxes    (B,M,4)
    const float* pad = (const float*)d_in[5];   // pad_gt_mask  (B,M,1)
    const int*   bg  = (n_in >= 7) ? (const int*)d_in[6] : nullptr;

    float* outL = (float*)d_out;                       // labels  (B*A)
    float* outB = outL + (size_t)BN*AN;                // bboxes  (B*A*4)
    float* outS = outL + (size_t)BN*AN*5;              // scores  (B*A*C)

    k_prep   <<<264, 1024>>>(ap);
    k_topk   <<<BN*MN/2, 256>>>(ps, pb, gl, gb, pad,
                                reinterpret_cast<float4*>(outS));
    k_assign <<<dim3((AN + 255)/256, BN), 256>>>(ps, pb, gl, gb, bg, outL, outB);
    k_sscore <<<(BN*AN + 255)/256, 256>>>(gl, outS);
}

// round 16
// speedup vs baseline: 3.8357x; 1.0331x over previous
#include <cuda_runtime.h>
#include <cstdint>

#define BN 32
#define AN 8400
#define CN 80
#define MN 64
#define TK 13
#define EPSF 1e-9f
#define NB 32                 // bins per dim
#define BINV 0.05f            // 1 / 20px
#define NBINS (NB*NB)
#define NF4   (BN*AN*CN/4)    // 5,376,000 float4s in the score tensor
#define ZE1   1792000         // third boundaries for the split zero-fill
#define ZE2   3584000

// ---------------- scratch (device globals; no allocation) ----------------
__device__ int    d_claim[BN*AN];     // (cnt<<16) | sum_of_m
__device__ float  d_maxmet[BN*MN];
__device__ float  d_maxiou[BN*MN];
__device__ int    d_ma[BN*AN];
__device__ float  d_alignv[BN*AN];
__device__ int    d_binstart[NBINS+1];
__device__ float2 d_bin_pt[AN];
__device__ int    d_bin_aid[AN];

// ---- prep: block 0 bins anchors; other blocks zero claims + 1st score third
__global__ void __launch_bounds__(1024)
k_prep(const float* __restrict__ ap, float4* __restrict__ outS4)
{
    const int tid = threadIdx.x;
    if (blockIdx.x != 0) {
        const float4 z = make_float4(0.f,0.f,0.f,0.f);
        int t = (blockIdx.x - 1)*1024 + tid;
        int step = (gridDim.x - 1)*1024;
        for (int i = t; i < BN*AN; i += step) d_claim[i] = 0;
        for (int i = t; i < ZE1; i += step) outS4[i] = z;      // 1st third
        if (blockIdx.x == 1) {
            d_maxmet[tid] = 0.f; d_maxmet[tid + 1024] = 0.f;
            d_maxiou[tid] = 0.f; d_maxiou[tid + 1024] = 0.f;
        }
        return;
    }
    __shared__ int s_cnt[NBINS];
    __shared__ int s_cur[NBINS];
    __shared__ int s_wsum[32];
    const int lane = tid & 31, wid = tid >> 5;
    const float2* ap2 = reinterpret_cast<const float2*>(ap);

    s_cnt[tid] = 0;
    __syncthreads();
    for (int i = tid; i < AN; i += 1024) {
        float2 pt = ap2[i];
        int bx = min(NB-1, max(0, (int)(pt.x * BINV)));
        int by = min(NB-1, max(0, (int)(pt.y * BINV)));
        atomicAdd(&s_cnt[by*NB + bx], 1);
    }
    __syncthreads();
    int v = s_cnt[tid];
    int x = v;
    #pragma unroll
    for (int o = 1; o < 32; o <<= 1) {
        int y = __shfl_up_sync(0xffffffffu, x, o);
        if (lane >= o) x += y;
    }
    if (lane == 31) s_wsum[wid] = x;
    __syncthreads();
    if (wid == 0) {
        int s = s_wsum[lane];
        #pragma unroll
        for (int o = 1; o < 32; o <<= 1) {
            int y = __shfl_up_sync(0xffffffffu, s, o);
            if (lane >= o) s += y;
        }
        s_wsum[lane] = s;
    }
    __syncthreads();
    int incl = x + (wid > 0 ? s_wsum[wid-1] : 0);
    int excl = incl - v;
    d_binstart[tid] = excl;
    if (tid == 1023) d_binstart[NBINS] = incl;   // == AN
    s_cur[tid] = excl;
    __syncthreads();
    for (int i = tid; i < AN; i += 1024) {
        float2 pt = ap2[i];
        int bx = min(NB-1, max(0, (int)(pt.x * BINV)));
        int by = min(NB-1, max(0, (int)(pt.y * BINV)));
        int pos = atomicAdd(&s_cur[by*NB + bx], 1);
        d_bin_pt[pos] = pt;
        d_bin_aid[pos] = i;
    }
}

// ------- top-13 (4 warps/gt) + 2nd third of the score zero-fill ------------
__global__ void __launch_bounds__(256)
k_topk(const float* __restrict__ ps, const float* __restrict__ pb,
       const int* __restrict__ gl, const float* __restrict__ gb,
       const float* __restrict__ pad, float4* __restrict__ outS4)
{
    {   // fire-and-forget streaming stores; drain overlaps the top-k below
        const float4 z = make_float4(0.f,0.f,0.f,0.f);
        for (int i = ZE1 + blockIdx.x*blockDim.x + threadIdx.x; i < ZE2;
             i += gridDim.x*blockDim.x)
            outS4[i] = z;
    }

    __shared__ float s_v[2][4][TK];
    __shared__ int   s_i[2][4][TK];
    const int wid  = threadIdx.x >> 5;
    const int lane = threadIdx.x & 31;
    const int gslot = wid >> 2;           // 2 gts per block
    const int q     = wid & 3;            // bin-row class (rows mod 4)
    const int W = blockIdx.x*2 + gslot;   // global gt id < 2048
    const int b = W >> 6;
    const int m = W & 63;
    const bool active = pad[b*MN + m] >= 0.5f;

    if (active) {
        const float4 g = reinterpret_cast<const float4*>(gb)[b*MN + m];
        const float gar = fmaxf(g.z - g.x, 0.f) * fmaxf(g.w - g.y, 0.f);
        const int lab = gl[b*MN + m];
        const float4* pb4 = reinterpret_cast<const float4*>(pb) + (size_t)b*AN;
        const float*  psb = ps + (size_t)b*AN*CN + lab;

        const int c0 = min(NB-1, max(0, (int)(g.x * BINV)));
        const int c1 = min(NB-1, max(0, (int)(g.z * BINV)));
        const int r0 = min(NB-1, max(0, (int)(g.y * BINV)));
        const int r1 = min(NB-1, max(0, (int)(g.w * BINV)));

        float tv[TK]; int ti[TK];
        #pragma unroll
        for (int k = 0; k < TK; k++) { tv[k] = 0.f; ti[k] = -1; }

        for (int r = r0 + q; r <= r1; r += 4) {
            const int s = d_binstart[r*NB + c0];
            const int e = d_binstart[r*NB + c1 + 1];   // contiguous span
            for (int i0 = s; i0 < e; i0 += 32) {
                const int i = i0 + lane;
                bool inside = false;
                if (i < e) {
                    float2 pt = d_bin_pt[i];
                    float dmin = fminf(fminf(pt.x - g.x, pt.y - g.y),
                                       fminf(g.z - pt.x, g.w - pt.y));
                    inside = dmin > EPSF;
                }
                if (__ballot_sync(0xffffffffu, inside)) {
                    float metr = 0.f; int aid = -1;
                    if (inside) {
                        aid = d_bin_aid[i];
                        float4 p = pb4[aid];
                        float parea = fmaxf(p.z - p.x, 0.f) * fmaxf(p.w - p.y, 0.f);
                        float ox = fminf(g.z, p.z) - fmaxf(g.x, p.x);
                        float oy = fminf(g.w, p.w) - fmaxf(g.y, p.y);
                        float ov = fmaxf(ox, 0.f) * fmaxf(oy, 0.f);
                        float iou = __fdividef(ov, gar + parea - ov + EPSF);
                        float sc = __ldg(psb + (size_t)aid*CN);
                        float i2 = iou * iou;
                        metr = sc * (i2 * i2 * i2);      // score^1 * iou^6
                    }
                    if (metr > tv[TK-1]) {
                        tv[TK-1] = metr; ti[TK-1] = aid;
                        #pragma unroll
                        for (int k = TK-1; k > 0; --k) {
                            if (tv[k] > tv[k-1]) {
                                float xx = tv[k]; tv[k] = tv[k-1]; tv[k-1] = xx;
                                int   yy = ti[k]; ti[k] = ti[k-1]; ti[k-1] = yy;
                            }
                        }
                    }
                }
            }
        }

        // extract this warp's sorted top-13 to smem (desc, tie -> lower index)
        #pragma unroll
        for (int r = 0; r < TK; r++) {
            float v = tv[0]; int idx = ti[0];
            #pragma unroll
            for (int o = 16; o; o >>= 1) {
                float ov = __shfl_xor_sync(0xffffffffu, v, o);
                int   oi = __shfl_xor_sync(0xffffffffu, idx, o);
                if (ov > v || (ov == v && (unsigned)oi < (unsigned)idx)) { v = ov; idx = oi; }
            }
            if (lane == r) { s_v[gslot][q][r] = v; s_i[gslot][q][r] = idx; }
            if (v > 0.f && idx == ti[0]) {            // unique winner lane pops
                #pragma unroll
                for (int j = 0; j < TK-1; j++) { tv[j] = tv[j+1]; ti[j] = ti[j+1]; }
                tv[TK-1] = 0.f; ti[TK-1] = -1;
            }
        }
    } else {
        if (lane < TK) { s_v[gslot][q][lane] = 0.f; s_i[gslot][q][lane] = -1; }
    }
    __syncthreads();

    // warp q==0 of each gt merges the 4 sorted 13-lists (52 entries, 2/lane)
    if (q == 0 && active) {
        const float* fv = &s_v[gslot][0][0];
        const int*   fi = &s_i[gslot][0][0];
        float v0 = fv[lane];        int i0 = fi[lane];           // 0..31
        float v1 = 0.f;             int i1 = -1;
        if (lane < 4*TK - 32) { v1 = fv[lane+32]; i1 = fi[lane+32]; } // 32..51
        #pragma unroll
        for (int r = 0; r < TK; r++) {
            bool p0 = (v0 > v1) || (v0 == v1 && (unsigned)i0 < (unsigned)i1);
            float lv = p0 ? v0 : v1;
            int   li = p0 ? i0 : i1;
            #pragma unroll
            for (int o = 16; o; o >>= 1) {
                float ov = __shfl_xor_sync(0xffffffffu, lv, o);
                int   oi = __shfl_xor_sync(0xffffffffu, li, o);
                if (ov > lv || (ov == lv && (unsigned)oi < (unsigned)li)) { lv = ov; li = oi; }
            }
            if (lv <= 0.f) break;                     // uniform
            if (i0 == li)      { atomicAdd(&d_claim[b*AN + li], (1 << 16) + m); v0 = 0.f; i0 = -1; }
            else if (i1 == li) { atomicAdd(&d_claim[b*AN + li], (1 << 16) + m); v1 = 0.f; i1 = -1; }
        }
    }
}

// ---- per-anchor assignment (bg fast path) + final third of zero-fill ------
__global__ void k_assign(const float* __restrict__ ps, const float* __restrict__ pb,
                         const int* __restrict__ gl, const float* __restrict__ gb,
                         const int* __restrict__ bgp,
                         float* __restrict__ outL, float* __restrict__ outB,
                         float4* __restrict__ outS4)
{
    {   // fire-and-forget; must precede k_sscore (guaranteed by graph order)
        const float4 z = make_float4(0.f,0.f,0.f,0.f);
        int t = (blockIdx.y*gridDim.x + blockIdx.x)*blockDim.x + threadIdx.x;
        int step = gridDim.x*gridDim.y*blockDim.x;
        for (int i = ZE2 + t; i < NF4; i += step) outS4[i] = z;
    }

    __shared__ float4 s_gbox[MN];
    __shared__ float  s_gar[MN];
    __shared__ int    s_lab[MN];
    int b = blockIdx.y;
    int tid = threadIdx.x;
    int a = blockIdx.x*blockDim.x + tid;
    int idx = b*AN + a;
    int claim = (a < AN) ? d_claim[idx] : 0;     // hoisted load
    if (tid < MN) {
        float4 g = reinterpret_cast<const float4*>(gb)[b*MN + tid];
        s_gbox[tid] = g;
        s_gar[tid] = fmaxf(g.z - g.x, 0.f) * fmaxf(g.w - g.y, 0.f);
        s_lab[tid] = gl[b*MN + tid];
    }
    __syncthreads();
    if (a >= AN) return;
    int c = claim >> 16;

    if (c == 0) {                               // ~92%: background, no pb load
        d_ma[idx] = -1;
        outL[idx] = (float)(bgp ? *bgp : 80);
        reinterpret_cast<float4*>(outB)[idx] = s_gbox[0];  // argmax of zeros -> gt 0
        return;
    }

    float4 p = reinterpret_cast<const float4*>(pb)[idx];
    float parea = fmaxf(p.z - p.x, 0.f) * fmaxf(p.w - p.y, 0.f);

    int m_a;
    if (c == 1) m_a = claim & 0xffff;
    else {                                      // multi: argmax IoU over ALL gts
        float best = -1.f; int bi2 = 0;
        for (int m = 0; m < MN; m++) {
            float4 g = s_gbox[m];
            float ox = fminf(g.z, p.z) - fmaxf(g.x, p.x);
            float oy = fminf(g.w, p.w) - fmaxf(g.y, p.y);
            float ov = fmaxf(ox, 0.f) * fmaxf(oy, 0.f);
            float iou = __fdividef(ov, s_gar[m] + parea - ov + EPSF);
            if (iou > best) { best = iou; bi2 = m; }
        }
        m_a = bi2;
    }

    float4 g = s_gbox[m_a];
    float ox = fminf(g.z, p.z) - fmaxf(g.x, p.x);
    float oy = fminf(g.w, p.w) - fmaxf(g.y, p.y);
    float ov = fmaxf(ox, 0.f) * fmaxf(oy, 0.f);
    float iou = __fdividef(ov, s_gar[m_a] + parea - ov + EPSF);
    float s = __ldg(ps + (size_t)idx*CN + s_lab[m_a]);
    float i2 = iou * iou;
    float alignv = s * (i2 * i2 * i2);
    atomicMax((int*)&d_maxmet[b*MN + m_a], __float_as_int(alignv)); // values >= 0
    atomicMax((int*)&d_maxiou[b*MN + m_a], __float_as_int(iou));

    d_ma[idx] = m_a;
    d_alignv[idx] = alignv;
    outL[idx] = (float)s_lab[m_a];
    reinterpret_cast<float4*>(outB)[idx] = g;
}

// ---------------- sparse score scatter (positives only) --------------------
__global__ void k_sscore(const int* __restrict__ gl, float* __restrict__ outS) {
    int idx = blockIdx.x*blockDim.x + threadIdx.x;
    if (idx >= BN*AN) return;
    int m_a = d_ma[idx];
    if (m_a < 0) return;
    int b = idx / AN;
    int bm = b*MN + m_a;
    float s = __fdividef(d_alignv[idx], d_maxmet[bm] + EPSF) * d_maxiou[bm];
    outS[(size_t)idx*CN + gl[bm]] = s;
}

// ---------------- launch ----------------
extern "C" void kernel_launch(void* const* d_in, const int* in_sizes, int n_in,
                              void* d_out, int out_size)
{
    const float* ps  = (const float*)d_in[0];   // pred_scores  (B,A,C)
    const float* pb  = (const float*)d_in[1];   // pred_bboxes  (B,A,4)
    const float* ap  = (const float*)d_in[2];   // anchor_points(A,2)
    const int*   gl  = (const int*)d_in[3];     // gt_labels    (B,M,1)
    const float* gb  = (const float*)d_in[4];   // gt_bboxes    (B,M,4)
    const float* pad = (const float*)d_in[5];   // pad_gt_mask  (B,M,1)
    const int*   bg  = (n_in >= 7) ? (const int*)d_in[6] : nullptr;

    float* outL = (float*)d_out;                       // labels  (B*A)
    float* outB = outL + (size_t)BN*AN;                // bboxes  (B*A*4)
    float* outS = outL + (size_t)BN*AN*5;              // scores  (B*A*C)
    float4* outS4 = reinterpret_cast<float4*>(outS);

    k_prep   <<<264, 1024>>>(ap, outS4);
    k_topk   <<<BN*MN/2, 256>>>(ps, pb, gl, gb, pad, outS4);
    k_assign <<<dim3((AN + 255)/256, BN), 256>>>(ps, pb, gl, gb, bg, outL, outB, outS4);
    k_sscore <<<(BN*AN + 255)/256, 256>>>(gl, outS);
}